// round 6
// baseline (speedup 1.0000x reference)
#include <cuda_runtime.h>
#include <cuda_fp16.h>
#include <cstdint>

// out[src] += edge_attr[e] * x[dst]   (E=1.6M, N=100k, D=32)
// Inputs: edge_index int32 [2,E], edge_attr f32 [E], x f32 [N,32]
// Output: f32 [N,32]
//
// Strategy: L2 sector-throughput is the wall (gather 4 + red 4 sectors/edge).
// Convert x to fp16 once (scratch in __device__ global), halving gather
// sectors (64B rows). Accumulate in fp32 via red.global.add.v4.f32.

#define XH_CAP (100000 * 32)
__device__ __half2 g_xh[XH_CAP / 2];

__device__ __forceinline__ void red_add_v4(float* addr, float4 v) {
    asm volatile("red.global.add.v4.f32 [%0], {%1, %2, %3, %4};"
                 :: "l"(addr), "f"(v.x), "f"(v.y), "f"(v.z), "f"(v.w)
                 : "memory");
}

__device__ __forceinline__ uint4 ldcg_u4(const void* p) {
    uint4 v;
    asm volatile("ld.global.cg.v4.b32 {%0, %1, %2, %3}, [%4];"
                 : "=r"(v.x), "=r"(v.y), "=r"(v.z), "=r"(v.w)
                 : "l"(p));
    return v;
}

__device__ __forceinline__ float4 ldcg_v4f(const float* p) {
    float4 v;
    asm volatile("ld.global.cg.v4.f32 {%0, %1, %2, %3}, [%4];"
                 : "=f"(v.x), "=f"(v.y), "=f"(v.z), "=f"(v.w)
                 : "l"(p));
    return v;
}

// fp32 -> fp16 conversion: each thread converts 4 floats -> 2 half2 (8B store)
__global__ void convert_kernel(const float* __restrict__ x, int n4) {
    int i = blockIdx.x * blockDim.x + threadIdx.x;
    int stride = gridDim.x * blockDim.x;
    for (; i < n4; i += stride) {
        float4 f = ((const float4*)x)[i];
        __half2 h0 = __floats2half2_rn(f.x, f.y);
        __half2 h1 = __floats2half2_rn(f.z, f.w);
        g_xh[i * 2]     = h0;
        g_xh[i * 2 + 1] = h1;
    }
}

#define EDGES_PER_WARP 32

// Warp = 8 edge-slots x 4 lanes; each lane covers 8 features (16B fp16 load,
// two float4 REDs). Gather is 2 sectors/edge instead of 4.
__global__ __launch_bounds__(256) void scatter_h_kernel(
        const int* __restrict__ edge_index,
        const float* __restrict__ edge_attr,
        float* __restrict__ out,
        int E) {
    int lane = threadIdx.x & 31;
    int slot = lane >> 2;            // 0..7 : which edge in the group of 8
    int fofs = (lane & 3) << 3;      // 0,8,16,24 : feature offset (in halfs)
    int warp = (blockIdx.x * blockDim.x + threadIdx.x) >> 5;
    int base = warp * EDGES_PER_WARP;
    if (base >= E) return;

    const __half* xh = (const __half*)g_xh;

    bool full = (base + EDGES_PER_WARP <= E);
    #pragma unroll
    for (int g = 0; g < 4; g++) {
        int e = base + g * 8 + slot;
        if (!full && e >= E) continue;

        int   src = __ldg(&edge_index[e]);
        int   dst = __ldg(&edge_index[E + e]);
        float a   = __ldg(&edge_attr[e]);

        uint4 h = ldcg_u4(xh + (long)dst * 32 + fofs);   // 8 halfs = 16B
        float2 f0 = __half22float2(*(__half2*)&h.x);
        float2 f1 = __half22float2(*(__half2*)&h.y);
        float2 f2 = __half22float2(*(__half2*)&h.z);
        float2 f3 = __half22float2(*(__half2*)&h.w);

        float4 v0 = make_float4(a * f0.x, a * f0.y, a * f1.x, a * f1.y);
        float4 v1 = make_float4(a * f2.x, a * f2.y, a * f3.x, a * f3.y);

        float* o = out + (long)src * 32 + fofs;
        red_add_v4(o,     v0);
        red_add_v4(o + 4, v1);
    }
}

// fp32 fallback (R4 style) in case x is larger than the scratch capacity.
__global__ __launch_bounds__(256) void scatter_f_kernel(
        const int* __restrict__ edge_index,
        const float* __restrict__ edge_attr,
        const float* __restrict__ x,
        float* __restrict__ out,
        int E) {
    int lane = threadIdx.x & 31;
    int slot = lane >> 3;
    int fofs = (lane & 7) << 2;
    int warp = (blockIdx.x * blockDim.x + threadIdx.x) >> 5;
    int base = warp * EDGES_PER_WARP;
    if (base >= E) return;

    for (int i = 0; i < 8; i++) {
        int e = base + i * 4 + slot;
        if (e < E) {
            int src = __ldg(&edge_index[e]);
            int dst = __ldg(&edge_index[E + e]);
            float a = __ldg(&edge_attr[e]);
            float4 v = ldcg_v4f(x + (long)dst * 32 + fofs);
            v.x *= a; v.y *= a; v.z *= a; v.w *= a;
            red_add_v4(out + (long)src * 32 + fofs, v);
        }
    }
}

extern "C" void kernel_launch(void* const* d_in, const int* in_sizes, int n_in,
                              void* d_out, int out_size) {
    const int*   edge_index = (const int*)d_in[0];
    const float* edge_attr  = (const float*)d_in[1];
    const float* x          = (const float*)d_in[2];
    float*       out        = (float*)d_out;

    int E  = in_sizes[0] / 2;
    int nx = in_sizes[2];

    // zero the (poisoned) output — graph-capturable
    cudaMemsetAsync(out, 0, (size_t)out_size * sizeof(float));

    int warps   = (E + EDGES_PER_WARP - 1) / EDGES_PER_WARP;
    int threads = 256;
    int blocks  = (warps * 32 + threads - 1) / threads;

    if (nx <= XH_CAP) {
        int n4 = nx / 4;
        int cb = (n4 + 255) / 256;
        if (cb > 4096) cb = 4096;
        convert_kernel<<<cb, 256>>>(x, n4);
        scatter_h_kernel<<<blocks, threads>>>(edge_index, edge_attr, out, E);
    } else {
        scatter_f_kernel<<<blocks, threads>>>(edge_index, edge_attr, x, out, E);
    }
}

// round 7
// speedup vs baseline: 1.3680x; 1.3680x over previous
#include <cuda_runtime.h>
#include <cuda_fp16.h>
#include <cstdint>

// out[src] += edge_attr[e] * x[dst]   (E=1.6M, N=100k, D=32)
// Inputs: edge_index int32 [2,E], edge_attr f32 [E], x f32 [N,32]
// Output: f32 [N,32]
//
// R7: R4's wavefront-optimal layout (8 lanes/edge, 4 edges per warp
// instruction, one RED.128 line per edge) + fp16 gather (LDG.64/lane)
// to halve gather sectors. fp32 accumulation via red.global.add.v4.f32.

#define XH_CAP (100000 * 32)
__device__ __half2 g_xh[XH_CAP / 2];

__device__ __forceinline__ void red_add_v4(float* addr, float4 v) {
    asm volatile("red.global.add.v4.f32 [%0], {%1, %2, %3, %4};"
                 :: "l"(addr), "f"(v.x), "f"(v.y), "f"(v.z), "f"(v.w)
                 : "memory");
}

__device__ __forceinline__ uint2 ldcg_u2(const void* p) {
    uint2 v;
    asm volatile("ld.global.cg.v2.b32 {%0, %1}, [%2];"
                 : "=r"(v.x), "=r"(v.y)
                 : "l"(p));
    return v;
}

__device__ __forceinline__ float4 ldcg_v4f(const float* p) {
    float4 v;
    asm volatile("ld.global.cg.v4.f32 {%0, %1, %2, %3}, [%4];"
                 : "=f"(v.x), "=f"(v.y), "=f"(v.z), "=f"(v.w)
                 : "l"(p));
    return v;
}

// fp32 -> fp16 conversion: each thread converts 4 floats -> 2 half2 (8B store)
__global__ void convert_kernel(const float* __restrict__ x, int n4) {
    int i = blockIdx.x * blockDim.x + threadIdx.x;
    int stride = gridDim.x * blockDim.x;
    for (; i < n4; i += stride) {
        float4 f = ((const float4*)x)[i];
        g_xh[i * 2]     = __floats2half2_rn(f.x, f.y);
        g_xh[i * 2 + 1] = __floats2half2_rn(f.z, f.w);
    }
}

#define EDGES_PER_WARP 32

// Warp = 4 edge-slots x 8 lanes; each lane covers 4 features.
// Gather: LDG.64 (4 halfs) -> 4 rows x 64B = 4 lines / warp instr.
// Reduce: RED.128 (4 floats) -> 4 rows x 128B = 4 lines / warp instr.
__global__ __launch_bounds__(256) void scatter_h_kernel(
        const int* __restrict__ edge_index,
        const float* __restrict__ edge_attr,
        float* __restrict__ out,
        int E) {
    int lane = threadIdx.x & 31;
    int slot = lane >> 3;            // 0..3 : which edge in the group of 4
    int f4   = lane & 7;             // 0..7 : which 4-feature chunk
    int warp = (blockIdx.x * blockDim.x + threadIdx.x) >> 5;
    int base = warp * EDGES_PER_WARP;
    if (base >= E) return;

    const __half* xh = (const __half*)g_xh;
    bool full = (base + EDGES_PER_WARP <= E);

    #pragma unroll
    for (int g = 0; g < 8; g++) {
        int e = base + g * 4 + slot;
        if (!full && e >= E) continue;

        int   src = __ldg(&edge_index[e]);
        int   dst = __ldg(&edge_index[E + e]);
        float a   = __ldg(&edge_attr[e]);

        uint2 h = ldcg_u2(xh + (long)dst * 32 + f4 * 4);   // 4 halfs = 8B
        float2 p0 = __half22float2(*(__half2*)&h.x);
        float2 p1 = __half22float2(*(__half2*)&h.y);

        float4 v = make_float4(a * p0.x, a * p0.y, a * p1.x, a * p1.y);
        red_add_v4(out + (long)src * 32 + f4 * 4, v);
    }
}

// fp32 fallback (R4 style) in case x is larger than the scratch capacity.
__global__ __launch_bounds__(256) void scatter_f_kernel(
        const int* __restrict__ edge_index,
        const float* __restrict__ edge_attr,
        const float* __restrict__ x,
        float* __restrict__ out,
        int E) {
    int lane = threadIdx.x & 31;
    int slot = lane >> 3;
    int fofs = (lane & 7) << 2;
    int warp = (blockIdx.x * blockDim.x + threadIdx.x) >> 5;
    int base = warp * EDGES_PER_WARP;
    if (base >= E) return;

    for (int i = 0; i < 8; i++) {
        int e = base + i * 4 + slot;
        if (e < E) {
            int src = __ldg(&edge_index[e]);
            int dst = __ldg(&edge_index[E + e]);
            float a = __ldg(&edge_attr[e]);
            float4 v = ldcg_v4f(x + (long)dst * 32 + fofs);
            v.x *= a; v.y *= a; v.z *= a; v.w *= a;
            red_add_v4(out + (long)src * 32 + fofs, v);
        }
    }
}

extern "C" void kernel_launch(void* const* d_in, const int* in_sizes, int n_in,
                              void* d_out, int out_size) {
    const int*   edge_index = (const int*)d_in[0];
    const float* edge_attr  = (const float*)d_in[1];
    const float* x          = (const float*)d_in[2];
    float*       out        = (float*)d_out;

    int E  = in_sizes[0] / 2;
    int nx = in_sizes[2];

    // zero the (poisoned) output — graph-capturable
    cudaMemsetAsync(out, 0, (size_t)out_size * sizeof(float));

    int warps   = (E + EDGES_PER_WARP - 1) / EDGES_PER_WARP;
    int threads = 256;
    int blocks  = (warps * 32 + threads - 1) / threads;

    if (nx <= XH_CAP) {
        int n4 = nx / 4;
        int cb = (n4 + 255) / 256;
        if (cb > 4096) cb = 4096;
        convert_kernel<<<cb, 256>>>(x, n4);
        scatter_h_kernel<<<blocks, threads>>>(edge_index, edge_attr, out, E);
    } else {
        scatter_f_kernel<<<blocks, threads>>>(edge_index, edge_attr, x, out, E);
    }
}